// round 15
// baseline (speedup 1.0000x reference)
#include <cuda_runtime.h>
#include <math.h>

#define B    8
#define V    32000
#define S    512
#define NC   125          // chunks in argmax pass (measured-good config)
#define VC   (V / NC)     // 256 v per chunk (compile-time trip count)
#define BSN  (B * S)      // 4096 (b,s) columns
#define P    (S - 4)      // 508 n-gram windows
#define HSZ  1024         // hash slots (2x load factor)

// -------- scratch (device globals; no allocation allowed) --------
// g_best[bs] = (monotonic_key(max) << 32) | ~argmax_token.
// Zero is the identity for max over finite floats; the last mask
// block re-zeroes it for the next graph replay.
__device__ unsigned long long g_best[BSN];
__device__ float g_gm  [BSN];         // global max (float)
__device__ int   g_list[BSN];         // worklist of masked bs
__device__ int   g_nlist;             // worklist length
__device__ int   g_done;              // mask-block completion counter

// order-preserving float -> uint32 (exact)
__device__ __forceinline__ unsigned int fkey(float f)
{
    unsigned int u = __float_as_uint(f);
    return u ^ ((unsigned int)(((int)u) >> 31) | 0x80000000u);
}
__device__ __forceinline__ float funkey(unsigned int k)
{
    unsigned int u = (k & 0x80000000u) ? (k ^ 0x80000000u) : ~k;
    return __uint_as_float(u);
}

__device__ __forceinline__ int khash(unsigned long long k)
{
    unsigned int h = (unsigned int)(k ^ (k >> 32));
    h *= 0x9E3779B1u;
    return (int)(h >> 22) & (HSZ - 1);
}

// ================================================================
// Kernel 1: streaming argmax per V-chunk + packed-u64 RED.MAX merge.
// grid = (125, 8) = 1000 blocks, 128 thr; thread owns 4 consecutive
// s via float4 streaming loads. (R11/R14 measured-best body.)
// ================================================================
__global__ __launch_bounds__(128) void k_argmax(const float* __restrict__ pred)
{
    const int c = blockIdx.x;
    const int b = blockIdx.y;
    const int t = threadIdx.x;
    const int s0 = t * 4;

    if (c == 0 && b == 0 && t == 0) g_nlist = 0;

    const float4* p = reinterpret_cast<const float4*>(
        pred + (size_t)(b * V + c * VC) * S + s0);
    const int pstep = S / 4;

    float m0 = -INFINITY, m1 = -INFINITY, m2 = -INFINITY, m3 = -INFINITY;
    int   i0 = 0, i1 = 0, i2 = 0, i3 = 0;

    int v = c * VC;
#pragma unroll 8
    for (int vv = 0; vv < VC; vv++, v++) {
        float4 x = __ldcs(p);          // streaming: evict-first
        p += pstep;
        // strict '>' + ascending v => first occurrence on exact ties
        if (x.x > m0) { m0 = x.x; i0 = v; }
        if (x.y > m1) { m1 = x.y; i1 = v; }
        if (x.z > m2) { m2 = x.z; i2 = v; }
        if (x.w > m3) { m3 = x.w; i3 = v; }
    }

    // pack + no-return atomic max merge (ties -> smaller token wins)
    const int bs = b * S + s0;
    atomicMax(&g_best[bs + 0],
        ((unsigned long long)fkey(m0) << 32) | (unsigned int)(~i0));
    atomicMax(&g_best[bs + 1],
        ((unsigned long long)fkey(m1) << 32) | (unsigned int)(~i1));
    atomicMax(&g_best[bs + 2],
        ((unsigned long long)fkey(m2) << 32) | (unsigned int)(~i2));
    atomicMax(&g_best[bs + 3],
        ((unsigned long long)fkey(m3) << 32) | (unsigned int)(~i3));

    // PDL release: this block's contribution to g_best is done.
    asm volatile("griddepcontrol.launch_dependents;" ::: "memory");
}

// ================================================================
// Kernel 2: 4-gram repeat mask via smem hash dedup (O(P) per batch)
// + worklist compaction; LAST block then does the exact-logsumexp
// worklist, scratch reset, and output write.
// grid = B = 8 blocks of 512. PDL-gated on g_best.
// ================================================================
__global__ __launch_bounds__(512) void k_masklse(const float* __restrict__ pred,
                                                 float* __restrict__ out)
{
    asm volatile("griddepcontrol.wait;" ::: "memory");

    const int b = blockIdx.x;
    const int t = threadIdx.x;

    __shared__ int                tok[S];
    __shared__ unsigned long long key[P];
    __shared__ unsigned long long slot_key[HSZ];
    __shared__ int                slot_min[HSZ];
    __shared__ unsigned char      rep[S];
    __shared__ float              red[512];
    __shared__ int                isLast;

    const unsigned long long EMPTY = ~0ull;   // keys are 60-bit

    // init hash table (2 slots/thread) + rep
    slot_key[t]       = EMPTY;
    slot_key[t + 512] = EMPTY;
    slot_min[t]       = 0x7FFFFFFF;
    slot_min[t + 512] = 0x7FFFFFFF;
    rep[t] = 0;

    // tokens + float max export
    unsigned long long be = g_best[b * S + t];
    tok[t] = (int)(~(unsigned int)be);
    g_gm[b * S + t] = funkey((unsigned int)(be >> 32));
    __syncthreads();

    // packed 4-gram keys (tokens < 32000 < 2^15 -> 60 bits)
    if (t < P) {
        key[t] = ((unsigned long long)tok[t]     << 45)
               | ((unsigned long long)tok[t + 1] << 30)
               | ((unsigned long long)tok[t + 2] << 15)
               |  (unsigned long long)tok[t + 3];
    }
    __syncthreads();

    // hash insert: record min position per distinct key
    if (t < P) {
        unsigned long long k = key[t];
        int h = khash(k);
        while (true) {
            unsigned long long prev = atomicCAS(&slot_key[h], EMPTY, k);
            if (prev == EMPTY || prev == k) {
                atomicMin(&slot_min[h], t);
                break;
            }
            h = (h + 1) & (HSZ - 1);
        }
    }
    __syncthreads();

    // lookup: rep[t] = exists j < t with key[j] == key[t]
    if (t < P) {
        unsigned long long k = key[t];
        int h = khash(k);
        while (slot_key[h] != k) h = (h + 1) & (HSZ - 1);
        rep[t] = (slot_min[h] < t) ? 1 : 0;
    }
    __syncthreads();

    // mask window + worklist: mask[t] = OR rep[q], q in [t-3, t] ∩ [0, P)
    {
        int lo = t - 3 > 0 ? t - 3 : 0;
        int hi = t < P - 1 ? t : P - 1;
        int msk = 0;
        for (int q = lo; q <= hi; q++) msk |= rep[q];
        if (msk) {
            int slot = atomicAdd(&g_nlist, 1);
            g_list[slot] = b * S + t;
        }
    }

    // ---- last-block-done: tail processing ----
    __syncthreads();
    if (t == 0) {
        __threadfence();
        isLast = (atomicAdd(&g_done, 1) == B - 1);
    }
    __syncthreads();
    if (!isLast) return;
    __threadfence();    // acquire: see all blocks' g_list/g_gm writes

    // reset g_best for next replay (all blocks have consumed it)
#pragma unroll
    for (int z = t; z < BSN; z += 512) g_best[z] = 0ull;

    // exact logsumexp penalty for worklisted columns (empty in
    // expectation for random tokens; exact for any input)
    const int n = g_nlist;
    float total = 0.0f;

    for (int wk = 0; wk < n; wk++) {
        const int bs = g_list[wk];
        const int bb = bs / S;
        const int s  = bs % S;
        const float m = g_gm[bs];

        const float* p = pred + (size_t)bb * V * S + s;

        float d = 0.0f;
        for (int v = t; v < V; v += 512)
            d += __expf(p[(size_t)v * S] - m);

        red[t] = d;
        __syncthreads();
        for (int st = 256; st > 0; st >>= 1) {
            if (t < st) red[t] += red[t + st];
            __syncthreads();
        }

        if (t == 0) {
            float D  = red[0];              // >= 1 (max term included)
            float lp = -logf(D);            // log_softmax at the argmax
            float pr = __expf(lp);
            float om = fmaxf(1.0f - pr, 1e-20f);
            total += -logf(om);
        }
        __syncthreads();
    }

    if (t == 0) {
        out[0] = total / (float)B;
        g_done = 0;                         // reset for next replay
    }
}

// ================================================================
extern "C" void kernel_launch(void* const* d_in, const int* in_sizes, int n_in,
                              void* d_out, int out_size)
{
    const float* pred = (const float*)d_in[0];

    dim3 g1(NC, B);
    k_argmax<<<g1, 128>>>(pred);

    // PDL launch: tail kernel's launch/prologue may overlap k_argmax;
    // griddepcontrol.wait gates data consumption.
    cudaLaunchConfig_t cfg = {};
    cfg.gridDim  = dim3(B, 1, 1);
    cfg.blockDim = dim3(512, 1, 1);
    cfg.dynamicSmemBytes = 0;
    cfg.stream = 0;

    cudaLaunchAttribute attr[1];
    attr[0].id = cudaLaunchAttributeProgrammaticStreamSerialization;
    attr[0].val.programmaticStreamSerializationAllowed = 1;
    cfg.attrs = attr;
    cfg.numAttrs = 1;

    float* outp = (float*)d_out;
    cudaLaunchKernelEx(&cfg, k_masklse, pred, outp);
}

// round 16
// speedup vs baseline: 1.0189x; 1.0189x over previous
#include <cuda_runtime.h>
#include <math.h>

#define B    8
#define V    32000
#define S    512
#define NC   125          // chunks in argmax pass
#define VC   (V / NC)     // 256 v per chunk
#define VH   (VC / 2)     // 128 v per half-stream
#define BSN  (B * S)      // 4096 (b,s) columns
#define P    (S - 4)      // 508 n-gram windows
#define MSPL 32           // mask splits per batch
#define MW   (S / MSPL)   // 16 mask outputs per block
#define NBLK (MSPL * B)   // 256 mask blocks

// -------- scratch (device globals; no allocation allowed) --------
// g_best[bs] = (monotonic_key(max) << 32) | ~argmax_token.
// Zero is the identity for max over finite floats; the last mask
// block re-zeroes it for the next graph replay.
__device__ unsigned long long g_best[BSN];
__device__ float g_gm  [BSN];         // global max (float)
__device__ int   g_list[BSN];         // worklist of masked bs
__device__ int   g_nlist;             // worklist length
__device__ int   g_done;              // mask-block completion counter

// order-preserving float -> uint32 (exact)
__device__ __forceinline__ unsigned int fkey(float f)
{
    unsigned int u = __float_as_uint(f);
    return u ^ ((unsigned int)(((int)u) >> 31) | 0x80000000u);
}
__device__ __forceinline__ float funkey(unsigned int k)
{
    unsigned int u = (k & 0x80000000u) ? (k ^ 0x80000000u) : ~k;
    return __uint_as_float(u);
}

// ================================================================
// Kernel 1: streaming argmax per V-chunk, TWO independent load/
// accumulate streams per thread (disjoint dependency trees -> more
// loads in flight), + packed-u64 RED.MAX merge.
// grid = (125, 8) = 1000 blocks, 128 thr; thread owns 4 consecutive
// s via float4 streaming loads.
// ================================================================
__global__ __launch_bounds__(128) void k_argmax(const float* __restrict__ pred)
{
    const int c = blockIdx.x;
    const int b = blockIdx.y;
    const int t = threadIdx.x;
    const int s0 = t * 4;

    if (c == 0 && b == 0 && t == 0) g_nlist = 0;

    const int pstep = S / 4;
    const float4* pA = reinterpret_cast<const float4*>(
        pred + (size_t)(b * V + c * VC) * S + s0);
    const float4* pB = pA + (size_t)VH * pstep;

    // stream A: v in [c*VC, c*VC+VH) ; stream B: [c*VC+VH, c*VC+VC)
    float a0 = -INFINITY, a1 = -INFINITY, a2 = -INFINITY, a3 = -INFINITY;
    float b0 = -INFINITY, b1 = -INFINITY, b2 = -INFINITY, b3 = -INFINITY;
    int   ia0 = 0, ia1 = 0, ia2 = 0, ia3 = 0;
    int   ib0 = 0, ib1 = 0, ib2 = 0, ib3 = 0;

    int vA = c * VC;
    int vB = vA + VH;
#pragma unroll 4
    for (int vv = 0; vv < VH; vv++, vA++, vB++) {
        float4 xA = __ldcs(pA); pA += pstep;
        float4 xB = __ldcs(pB); pB += pstep;
        // strict '>' + ascending v => first occurrence on exact ties
        if (xA.x > a0) { a0 = xA.x; ia0 = vA; }
        if (xA.y > a1) { a1 = xA.y; ia1 = vA; }
        if (xA.z > a2) { a2 = xA.z; ia2 = vA; }
        if (xA.w > a3) { a3 = xA.w; ia3 = vA; }
        if (xB.x > b0) { b0 = xB.x; ib0 = vB; }
        if (xB.y > b1) { b1 = xB.y; ib1 = vB; }
        if (xB.z > b2) { b2 = xB.z; ib2 = vB; }
        if (xB.w > b3) { b3 = xB.w; ib3 = vB; }
    }

    // merge halves: all A indices < B indices, so strict '>' of B
    // over A keeps the first occurrence on exact ties
    if (b0 > a0) { a0 = b0; ia0 = ib0; }
    if (b1 > a1) { a1 = b1; ia1 = ib1; }
    if (b2 > a2) { a2 = b2; ia2 = ib2; }
    if (b3 > a3) { a3 = b3; ia3 = ib3; }

    // pack + no-return atomic max merge (ties -> smaller token wins)
    const int bs = b * S + s0;
    atomicMax(&g_best[bs + 0],
        ((unsigned long long)fkey(a0) << 32) | (unsigned int)(~ia0));
    atomicMax(&g_best[bs + 1],
        ((unsigned long long)fkey(a1) << 32) | (unsigned int)(~ia1));
    atomicMax(&g_best[bs + 2],
        ((unsigned long long)fkey(a2) << 32) | (unsigned int)(~ia2));
    atomicMax(&g_best[bs + 3],
        ((unsigned long long)fkey(a3) << 32) | (unsigned int)(~ia3));

    // PDL release: this block's contribution to g_best is done.
    asm volatile("griddepcontrol.launch_dependents;" ::: "memory");
}

// ================================================================
// Kernel 2 (R14 measured-best tail): 4-gram repeat mask + worklist
// compaction; LAST block runs exact logsumexp over the worklist,
// resets scratch, writes the output. grid = (MSPL, B) = 256 blocks.
// ================================================================
__global__ __launch_bounds__(256) void k_masklse(const float* __restrict__ pred,
                                                 float* __restrict__ out)
{
    asm volatile("griddepcontrol.wait;" ::: "memory");

    const int b    = blockIdx.y;
    const int p0   = blockIdx.x * MW;
    const int t    = threadIdx.x;
    const int w    = t >> 5;            // warp 0..7
    const int lane = t & 31;

    __shared__ int                tok[S];
    __shared__ unsigned long long key[S];       // P used
    __shared__ unsigned char      rep[MW + 4];
    __shared__ int                isLast;
    __shared__ float              red[256];

    // tokens from packed best (low 32 bits = ~token)
    unsigned long long be0 = g_best[b * S + t];
    unsigned long long be1 = g_best[b * S + t + 256];
    tok[t]       = (int)(~(unsigned int)be0);
    tok[t + 256] = (int)(~(unsigned int)be1);
    if (t < MW + 4) rep[t] = 0;
    __syncthreads();

    // export float max (block 0 of each batch only; duplicate-safe)
    if (blockIdx.x == 0) {
        g_gm[b * S + t]       = funkey((unsigned int)(be0 >> 32));
        g_gm[b * S + t + 256] = funkey((unsigned int)(be1 >> 32));
    }

    // packed 4-gram keys (tokens < 32000 < 2^15 -> 60 bits)
#pragma unroll
    for (int tt = t; tt < P; tt += 256) {
        key[tt] = ((unsigned long long)tok[tt]     << 45)
                | ((unsigned long long)tok[tt + 1] << 30)
                | ((unsigned long long)tok[tt + 2] << 15)
                |  (unsigned long long)tok[tt + 3];
    }
    __syncthreads();

    // warp-parallel duplicate scan: warp w covers li = w, w+8, w+16
#pragma unroll
    for (int r = 0; r < 3; r++) {
        int li  = w + 8 * r;            // 0..23; need 0..MW+2
        int pos = p0 - 3 + li;
        if (li < MW + 3 && pos >= 0 && pos < P) {
            unsigned long long k = key[pos];
            bool eq = false;
            int nIt = (pos + 31) >> 5;
            for (int it = 0; it < nIt; it++) {
                int j = lane + (it << 5);
                eq |= (j < pos) && (key[j] == k);
            }
            if (__any_sync(0xffffffffu, eq) && lane == 0) rep[li] = 1;
        }
    }
    __syncthreads();

    // mask outputs for positions [p0, p0+MW)
    if (t < MW) {
        int pos = p0 + t;
        int lo  = pos - 3 > 0 ? pos - 3 : 0;
        int hi  = pos < P - 1 ? pos : P - 1;
        int msk = 0;
        for (int q = lo; q <= hi; q++)
            msk |= rep[q - p0 + 3];

        if (msk) {
            int slot = atomicAdd(&g_nlist, 1);
            g_list[slot] = b * S + pos;
        }
    }

    // ---- last-block-done: tail processing ----
    __syncthreads();
    if (t == 0) {
        __threadfence();
        isLast = (atomicAdd(&g_done, 1) == NBLK - 1);
    }
    __syncthreads();
    if (!isLast) return;
    __threadfence();    // acquire: see all blocks' g_list/g_gm writes

    // reset g_best for next replay (all blocks have consumed it)
    for (int z = t; z < BSN; z += 256) g_best[z] = 0ull;

    // exact logsumexp penalty for worklisted columns (empty in
    // expectation for random tokens; exact for any input)
    const int n = g_nlist;
    float total = 0.0f;

    for (int wk = 0; wk < n; wk++) {
        const int bs = g_list[wk];
        const int bb = bs / S;
        const int s  = bs % S;
        const float m = g_gm[bs];

        const float* p = pred + (size_t)bb * V * S + s;

        float d = 0.0f;
        for (int v = t; v < V; v += 256)
            d += __expf(p[(size_t)v * S] - m);

        red[t] = d;
        __syncthreads();
        for (int st = 128; st > 0; st >>= 1) {
            if (t < st) red[t] += red[t + st];
            __syncthreads();
        }

        if (t == 0) {
            float D  = red[0];              // >= 1 (max term included)
            float lp = -logf(D);            // log_softmax at the argmax
            float pr = __expf(lp);
            float om = fmaxf(1.0f - pr, 1e-20f);
            total += -logf(om);
        }
        __syncthreads();
    }

    if (t == 0) {
        out[0] = total / (float)B;
        g_done = 0;                         // reset for next replay
    }
}

// ================================================================
extern "C" void kernel_launch(void* const* d_in, const int* in_sizes, int n_in,
                              void* d_out, int out_size)
{
    const float* pred = (const float*)d_in[0];

    dim3 g1(NC, B);
    k_argmax<<<g1, 128>>>(pred);

    // PDL launch of the tail kernel (graph-capturable).
    cudaLaunchConfig_t cfg = {};
    cfg.gridDim  = dim3(MSPL, B, 1);
    cfg.blockDim = dim3(256, 1, 1);
    cfg.dynamicSmemBytes = 0;
    cfg.stream = 0;

    cudaLaunchAttribute attr[1];
    attr[0].id = cudaLaunchAttributeProgrammaticStreamSerialization;
    attr[0].val.programmaticStreamSerializationAllowed = 1;
    cfg.attrs = attr;
    cfg.numAttrs = 1;

    float* outp = (float*)d_out;
    cudaLaunchKernelEx(&cfg, k_masklse, pred, outp);
}